// round 4
// baseline (speedup 1.0000x reference)
#include <cuda_runtime.h>
#include <cstdint>

// LinearReg: sum over rows/groups of L2 norm of 25-element groups of
// weight[N,800] f32, averaged over rows, scaled by 0.001 * c_omega.
// Single fused launch; 4-stage cp.async pipeline (one barrier per chunk);
// decoupled last-block reduction.

#define GROUPS 32
#define GSIZE 25
#define ROW_ELEMS 800
#define RPB 4                                    // rows per chunk
#define STAGES 4
#define THREADS 256
#define CHUNK_FLOATS (RPB * ROW_ELEMS)           // 3200
#define CHUNK_VEC (CHUNK_FLOATS / 4)             // 800 float4
#define STAGE_BYTES (CHUNK_FLOATS * 4)           // 12800
#define SMEM_BYTES (STAGES * STAGE_BYTES)        // 51200
#define MAXBLOCKS 4096

__device__ float g_partials[MAXBLOCKS];
__device__ unsigned g_count = 0;    // last block resets -> replay-deterministic

__device__ __forceinline__ void cp_async16(uint32_t saddr, const float4* gptr) {
    asm volatile("cp.async.cg.shared.global [%0], [%1], 16;\n"
                 :: "r"(saddr), "l"(__cvta_generic_to_global(gptr)));
}
__device__ __forceinline__ void cp_commit() {
    asm volatile("cp.async.commit_group;\n");
}
__device__ __forceinline__ void cp_wait2() {
    asm volatile("cp.async.wait_group 2;\n");
}
__device__ __forceinline__ void cp_wait_all() {
    asm volatile("cp.async.wait_group 0;\n");
}

// Issue one chunk's staging (predicated on global bounds). Always safe to
// call with an out-of-range chunk (issues nothing).
__device__ __forceinline__ void stage_chunk(
    const float4* __restrict__ src, uint32_t sdst,
    int chunk, int nchunks, long long total_vec)
{
    if (chunk < nchunks) {
        long long gv = (long long)chunk * CHUNK_VEC;
        #pragma unroll
        for (int k = 0; k < (CHUNK_VEC + THREADS - 1) / THREADS; k++) {
            int i = threadIdx.x + k * THREADS;
            if (i < CHUNK_VEC && gv + i < total_vec)
                cp_async16(sdst + i * 16, &src[gv + i]);
        }
    }
}

__global__ __launch_bounds__(THREADS) void lr_fused_kernel(
    const float* __restrict__ w, const unsigned* __restrict__ c_omega_raw,
    float* __restrict__ out, int n)
{
    extern __shared__ float s[];                  // [STAGES][CHUNK_FLOATS]
    __shared__ float warpsum[THREADS / 32];
    __shared__ double warpsumd[THREADS / 32];
    __shared__ int is_last;

    const int nchunks = (n + RPB - 1) / RPB;
    const long long total_vec = (long long)n * (ROW_ELEMS / 4);
    const uint32_t sbase = (uint32_t)__cvta_generic_to_shared(s);
    const float4* __restrict__ src = (const float4*)w;
    const int G = gridDim.x;

    float total = 0.0f;

    // -- prologue: stage first 3 chunks into stages 0,1,2 (3 commit groups) --
    stage_chunk(src, sbase + 0 * STAGE_BYTES, blockIdx.x + 0 * G, nchunks, total_vec);
    cp_commit();
    stage_chunk(src, sbase + 1 * STAGE_BYTES, blockIdx.x + 1 * G, nchunks, total_vec);
    cp_commit();
    stage_chunk(src, sbase + 2 * STAGE_BYTES, blockIdx.x + 2 * G, nchunks, total_vec);
    cp_commit();

    // compute mapping: 4 rows x 32 groups, 2 threads per group (13+12 elems)
    const int row  = threadIdx.x >> 6;            // 0..3
    const int sub  = threadIdx.x & 63;
    const int grp  = sub >> 1;                    // 0..31
    const int half = sub & 1;                     // 0: elems 0..12, 1: 13..24

    int buf = 0;
    for (int chunk = blockIdx.x; chunk < nchunks; chunk += G) {
        cp_wait2();            // chunk's data arrived (issuing-thread scope)
        __syncthreads();       // CTA-wide visibility + prior compute retired

        // issue chunk+3*G into the stage last used 4 chunks ago (safe: the
        // barrier above ordered all reads of that stage before this write)
        stage_chunk(src, sbase + ((buf + 3) & 3) * STAGE_BYTES,
                    chunk + 3 * G, nchunks, total_vec);
        cp_commit();

        // -- compute on current stage --
        int rows = n - chunk * RPB;
        if (rows > RPB) rows = RPB;
        float acc = 0.0f;
        if (row < rows) {
            const float* p = s + buf * CHUNK_FLOATS + row * ROW_ELEMS
                           + grp * GSIZE + half * 13;
            #pragma unroll
            for (int i = 0; i < 12; i++)
                acc = fmaf(p[i], p[i], acc);
            if (!half) acc = fmaf(p[12], p[12], acc);   // 13th elem of half 0
        }
        acc += __shfl_xor_sync(0xffffffffu, acc, 1);    // pair-combine group
        if (!half && row < rows)
            total += sqrtf(acc);

        buf = (buf + 1) & 3;
    }
    cp_wait_all();             // drain dangling prefetch groups

    // -- block reduction of per-thread norm sums --
    #pragma unroll
    for (int o = 16; o > 0; o >>= 1)
        total += __shfl_xor_sync(0xffffffffu, total, o);
    if ((threadIdx.x & 31) == 0)
        warpsum[threadIdx.x >> 5] = total;
    __syncthreads();

    if (threadIdx.x == 0) {
        float bsum = 0.0f;
        #pragma unroll
        for (int i = 0; i < THREADS / 32; i++)
            bsum += warpsum[i];
        g_partials[blockIdx.x] = bsum;
        __threadfence();                         // publish partial before ticket
        unsigned t = atomicAdd(&g_count, 1u);
        is_last = (t == gridDim.x - 1);
    }
    __syncthreads();

    if (is_last) {
        double v = 0.0;
        for (int i = threadIdx.x; i < (int)gridDim.x; i += THREADS)
            v += (double)__ldcg(&g_partials[i]);    // bypass L1
        #pragma unroll
        for (int o = 16; o > 0; o >>= 1)
            v += __shfl_xor_sync(0xffffffffu, v, o);
        if ((threadIdx.x & 31) == 0)
            warpsumd[threadIdx.x >> 5] = v;
        __syncthreads();
        if (threadIdx.x == 0) {
            double sum = 0.0;
            #pragma unroll
            for (int i = 0; i < THREADS / 32; i++)
                sum += warpsumd[i];
            // c_omega is the python int 1; accept int-typed or f32-typed
            // scalar deterministically by bit-pattern magnitude.
            unsigned u = *c_omega_raw;
            float c = (u < (1u << 30)) ? (float)(int)u : __uint_as_float(u);
            out[0] = (float)(sum / (double)n * 0.001 * (double)c);
            g_count = 0;                        // restore for next graph replay
        }
    }
}

extern "C" void kernel_launch(void* const* d_in, const int* in_sizes, int n_in,
                              void* d_out, int out_size)
{
    const float* w = (const float*)d_in[0];
    const unsigned* c_omega = (const unsigned*)d_in[1];
    int n = in_sizes[0] / (GROUPS * GSIZE);   // 100000

    cudaFuncSetAttribute(lr_fused_kernel,
                         cudaFuncAttributeMaxDynamicSharedMemorySize, SMEM_BYTES);

    int nchunks = (n + RPB - 1) / RPB;
    int blocks = 152 * 4;                      // 4 blocks/SM (51.2KB smem each)
    if (blocks > nchunks) blocks = nchunks;
    if (blocks > MAXBLOCKS) blocks = MAXBLOCKS;

    lr_fused_kernel<<<blocks, THREADS, SMEM_BYTES>>>(w, c_omega, (float*)d_out, n);
}

// round 5
// speedup vs baseline: 1.2058x; 1.2058x over previous
#include <cuda_runtime.h>
#include <cstdint>

// LinearReg: sum over rows/groups of L2 norms of 25-element groups of
// weight[N,800] f32, /N, * 0.001 * c_omega.
// TMA-bulk producer warp + mbarrier ring; no __syncthreads in hot loop.

#define GROUPS 32
#define GSIZE 25
#define ROW_ELEMS 800
#define RPB 8                                    // rows per chunk
#define STAGES 4
#define CONSUMERS 256
#define THREADS 288                              // 8 consumer warps + 1 producer
#define CHUNK_FLOATS (RPB * ROW_ELEMS)           // 6400
#define CHUNK_BYTES (CHUNK_FLOATS * 4)           // 25600
#define SMEM_BYTES (STAGES * CHUNK_BYTES)        // 102400
#define MAXBLOCKS 4096

__device__ float g_partials[MAXBLOCKS];
__device__ unsigned g_count = 0;   // last block resets -> replay-deterministic

#define MBAR_INIT(addr, cnt) \
    asm volatile("mbarrier.init.shared.b64 [%0], %1;" :: "r"(addr), "r"(cnt) : "memory")
#define MBAR_ARRIVE(addr) \
    asm volatile("mbarrier.arrive.shared.b64 _, [%0];" :: "r"(addr) : "memory")
#define MBAR_EXPECT_TX(addr, bytes) \
    asm volatile("mbarrier.arrive.expect_tx.shared.b64 _, [%0], %1;" \
                 :: "r"(addr), "r"(bytes) : "memory")
#define MBAR_WAIT(addr, parity) do {                                          \
    asm volatile(                                                             \
        "{\n\t"                                                               \
        ".reg .pred P;\n\t"                                                   \
        "WAIT_%=:\n\t"                                                        \
        "mbarrier.try_wait.parity.acquire.cta.shared::cta.b64 P, [%0], %1, 0x989680;\n\t" \
        "@P bra DONE_%=;\n\t"                                                 \
        "bra WAIT_%=;\n\t"                                                    \
        "DONE_%=:\n\t"                                                        \
        "}" :: "r"(addr), "r"(parity) : "memory");                            \
} while (0)

__device__ __forceinline__ void tma_bulk_1d(uint32_t sdst, const void* gsrc,
                                            uint32_t bytes, uint32_t mbar) {
    asm volatile(
        "cp.async.bulk.shared::cluster.global.mbarrier::complete_tx::bytes "
        "[%0], [%1], %2, [%3];"
        :: "r"(sdst), "l"(__cvta_generic_to_global(gsrc)), "r"(bytes), "r"(mbar)
        : "memory");
}

__global__ __launch_bounds__(THREADS) void lr_fused_kernel(
    const float* __restrict__ w, const unsigned* __restrict__ c_omega_raw,
    float* __restrict__ out, int n)
{
    extern __shared__ float s[];                 // [STAGES][CHUNK_FLOATS]
    __shared__ __align__(8) unsigned long long mbar_full[STAGES];
    __shared__ __align__(8) unsigned long long mbar_empty[STAGES];
    __shared__ float warpsum[THREADS / 32];
    __shared__ double warpsumd[THREADS / 32];
    __shared__ int is_last;

    const int nchunks = (n + RPB - 1) / RPB;
    const uint32_t sbase = (uint32_t)__cvta_generic_to_shared(s);
    const uint32_t full0  = (uint32_t)__cvta_generic_to_shared(mbar_full);
    const uint32_t empty0 = (uint32_t)__cvta_generic_to_shared(mbar_empty);
    const int G = gridDim.x;

    if (threadIdx.x == 0) {
        #pragma unroll
        for (int i = 0; i < STAGES; i++) {
            MBAR_INIT(full0 + i * 8, 1);           // completed by TMA tx
            MBAR_INIT(empty0 + i * 8, CONSUMERS);  // all consumers arrive
        }
        asm volatile("fence.proxy.async.shared::cta;" ::: "memory");
    }
    __syncthreads();

    float total = 0.0f;

    if (threadIdx.x >= CONSUMERS) {
        // ---- producer warp (one elected thread issues TMA) ----
        if (threadIdx.x == CONSUMERS) {
            int st = 0, ph = 1;                    // first empty-waits pass
            for (int chunk = blockIdx.x; chunk < nchunks; chunk += G) {
                MBAR_WAIT(empty0 + st * 8, (uint32_t)ph);
                int rows = n - chunk * RPB;
                if (rows > RPB) rows = RPB;
                uint32_t bytes = (uint32_t)rows * ROW_ELEMS * 4;
                uint32_t fb = full0 + st * 8;
                MBAR_EXPECT_TX(fb, bytes);
                tma_bulk_1d(sbase + st * CHUNK_BYTES,
                            w + (long long)chunk * CHUNK_FLOATS, bytes, fb);
                if (++st == STAGES) { st = 0; ph ^= 1; }
            }
        }
    } else {
        // ---- consumer warps: row = warp, group = lane (conflict-free) ----
        const int row = threadIdx.x >> 5;
        const int grp = threadIdx.x & 31;
        int st = 0, ph = 0;
        for (int chunk = blockIdx.x; chunk < nchunks; chunk += G) {
            MBAR_WAIT(full0 + st * 8, (uint32_t)ph);
            int rows = n - chunk * RPB;
            if (rows > RPB) rows = RPB;
            if (row < rows) {
                const float* p = s + st * CHUNK_FLOATS + row * ROW_ELEMS
                               + grp * GSIZE;
                float acc = 0.0f;
                #pragma unroll
                for (int i = 0; i < GSIZE; i++)
                    acc = fmaf(p[i], p[i], acc);
                total += sqrtf(acc);
            }
            MBAR_ARRIVE(empty0 + st * 8);
            if (++st == STAGES) { st = 0; ph ^= 1; }
        }
    }
    __syncthreads();   // everyone done; all TMA issued were consumed

    // ---- block reduction over all 9 warps (producer contributes 0) ----
    #pragma unroll
    for (int o = 16; o > 0; o >>= 1)
        total += __shfl_xor_sync(0xffffffffu, total, o);
    if ((threadIdx.x & 31) == 0)
        warpsum[threadIdx.x >> 5] = total;
    __syncthreads();

    if (threadIdx.x == 0) {
        float bsum = 0.0f;
        #pragma unroll
        for (int i = 0; i < THREADS / 32; i++)
            bsum += warpsum[i];
        g_partials[blockIdx.x] = bsum;
        __threadfence();                         // publish partial before ticket
        unsigned t = atomicAdd(&g_count, 1u);
        is_last = (t == gridDim.x - 1);
    }
    __syncthreads();

    if (is_last) {
        double v = 0.0;
        for (int i = threadIdx.x; i < (int)gridDim.x; i += THREADS)
            v += (double)__ldcg(&g_partials[i]);    // bypass L1
        #pragma unroll
        for (int o = 16; o > 0; o >>= 1)
            v += __shfl_xor_sync(0xffffffffu, v, o);
        if ((threadIdx.x & 31) == 0)
            warpsumd[threadIdx.x >> 5] = v;
        __syncthreads();
        if (threadIdx.x == 0) {
            double sum = 0.0;
            #pragma unroll
            for (int i = 0; i < THREADS / 32; i++)
                sum += warpsumd[i];
            // c_omega is python int 1; accept int-typed or f32-typed scalar
            // deterministically by bit-pattern magnitude.
            unsigned u = *c_omega_raw;
            float c = (u < (1u << 30)) ? (float)(int)u : __uint_as_float(u);
            out[0] = (float)(sum / (double)n * 0.001 * (double)c);
            g_count = 0;                        // restore for next graph replay
        }
    }
}

extern "C" void kernel_launch(void* const* d_in, const int* in_sizes, int n_in,
                              void* d_out, int out_size)
{
    const float* w = (const float*)d_in[0];
    const unsigned* c_omega = (const unsigned*)d_in[1];
    int n = in_sizes[0] / (GROUPS * GSIZE);   // 100000

    cudaFuncSetAttribute(lr_fused_kernel,
                         cudaFuncAttributeMaxDynamicSharedMemorySize, SMEM_BYTES);

    int nchunks = (n + RPB - 1) / RPB;
    int blocks = 152 * 2;                      // 2 blocks/SM, 102.4KB smem each
    if (blocks > nchunks) blocks = nchunks;
    if (blocks > MAXBLOCKS) blocks = MAXBLOCKS;

    lr_fused_kernel<<<blocks, THREADS, SMEM_BYTES>>>(w, c_omega, (float*)d_out, n);
}